// round 4
// baseline (speedup 1.0000x reference)
#include <cuda_runtime.h>

// out[b] = sum_j exp(-K2_j) * K2_j / sum_j exp(-K2_j),
// K2_j = (x_j - mean(x))^2 over all_atom_features of batch b.
// (softmax_j over -(Q2_i + K2_j) cancels Q2_i exactly -> cdr3 input unused.
//  K2 >= 0 so exp(-K2) <= 1: no max-shift needed for fp32 safety.)

#define M 8192
#define NTHREADS 1024
#define NWARPS (NTHREADS / 32)

__global__ __launch_bounds__(NTHREADS)
void invariant_cross_attention_kernel(const float4* __restrict__ atom4,
                                      float* __restrict__ out) {
    __shared__ float  red1[NWARPS];
    __shared__ float2 red2[NWARPS];

    const int tid  = threadIdx.x;
    const int lane = tid & 31;
    const int wid  = tid >> 5;
    const float4* __restrict__ x4 = atom4 + (size_t)blockIdx.x * (M / 4);

    // ---- Load 8 elements into registers (2x LDG.128, issued back-to-back) ----
    float4 v0 = x4[tid];
    float4 v1 = x4[tid + NTHREADS];

    // ---- Reduction 1: sum -> mean ----
    float sum = ((v0.x + v0.y) + (v0.z + v0.w)) + ((v1.x + v1.y) + (v1.z + v1.w));
    #pragma unroll
    for (int o = 16; o > 0; o >>= 1) sum += __shfl_down_sync(0xffffffffu, sum, o);
    if (lane == 0) red1[wid] = sum;
    __syncthreads();
    float total;
    {
        // every thread reduces the 32 warp partials redundantly (no second
        // barrier + broadcast needed; NWARPS==32 values sit in one smem line)
        float t = red1[lane];
        #pragma unroll
        for (int o = 16; o > 0; o >>= 1) t += __shfl_down_sync(0xffffffffu, t, o);
        total = __shfl_sync(0xffffffffu, t, 0);
    }
    const float mean = total * (1.0f / (float)M);

    // ---- Pass 2 (registers only): s = sum exp(-k2), num = sum exp(-k2)*k2 ----
    float s = 0.0f, num = 0.0f;
    float vals[8] = {v0.x, v0.y, v0.z, v0.w, v1.x, v1.y, v1.z, v1.w};
    #pragma unroll
    for (int k = 0; k < 8; k++) {
        float d  = vals[k] - mean;
        float k2 = d * d;
        float e  = __expf(-k2);
        s   += e;
        num  = fmaf(e, k2, num);
    }

    // ---- Reduction 2: joint (s, num) ----
    #pragma unroll
    for (int o = 16; o > 0; o >>= 1) {
        s   += __shfl_down_sync(0xffffffffu, s, o);
        num += __shfl_down_sync(0xffffffffu, num, o);
    }
    if (lane == 0) red2[wid] = make_float2(s, num);
    __syncthreads();
    if (wid == 0) {
        float2 t = red2[lane];
        #pragma unroll
        for (int o = 16; o > 0; o >>= 1) {
            t.x += __shfl_down_sync(0xffffffffu, t.x, o);
            t.y += __shfl_down_sync(0xffffffffu, t.y, o);
        }
        if (lane == 0) out[blockIdx.x] = t.y / t.x;
    }
}

extern "C" void kernel_launch(void* const* d_in, const int* in_sizes, int n_in,
                              void* d_out, int out_size) {
    // d_in[0] = cdr3_features  [4, 2048, 1] (mathematically irrelevant; unused)
    // d_in[1] = all_atom_features [4, 8192, 1]
    const float4* atom4 = (const float4*)d_in[1];
    float* out = (float*)d_out;
    const int B = in_sizes[1] / M;   // 4
    invariant_cross_attention_kernel<<<B, NTHREADS>>>(atom4, out);
}

// round 6
// speedup vs baseline: 1.0483x; 1.0483x over previous
#include <cuda_runtime.h>

// out[b] = sum_j exp(-K2_j) * K2_j / sum_j exp(-K2_j),
// K2_j = (x_j - mean(x))^2 over all_atom_features of batch b.
// (softmax_j over -(Q2_i + K2_j) cancels Q2_i exactly -> cdr3 input unused.
//  K2 >= 0 so exp(-K2) <= 1: no max-shift needed for fp32 safety.)
//
// Latency-bound regime (grid=4, all pipes ~0%): minimize block ramp/drain and
// barrier cost -> 8 warps/block, 32 elems/thread in registers, MLP=8 loads.

#define M 8192
#define NTHREADS 256
#define NWARPS (NTHREADS / 32)
#define ELEMS 32                 // per thread
#define VECS  (ELEMS / 4)        // 8 float4 loads per thread

__global__ __launch_bounds__(NTHREADS)
void invariant_cross_attention_kernel(const float4* __restrict__ atom4,
                                      float* __restrict__ out) {
    __shared__ float  red1[NWARPS];
    __shared__ float2 red2[NWARPS];

    const int tid  = threadIdx.x;
    const int lane = tid & 31;
    const int wid  = tid >> 5;
    const float4* __restrict__ x4 = atom4 + (size_t)blockIdx.x * (M / 4);

    // ---- Front-batched loads: 8x LDG.128 in flight (MLP=8) ----
    float4 v[VECS];
    #pragma unroll
    for (int k = 0; k < VECS; k++) v[k] = x4[tid + k * NTHREADS];

    // ---- Reduction 1: sum -> mean ----
    float sum = 0.0f;
    #pragma unroll
    for (int k = 0; k < VECS; k++)
        sum += ((v[k].x + v[k].y) + (v[k].z + v[k].w));
    #pragma unroll
    for (int o = 16; o > 0; o >>= 1) sum += __shfl_down_sync(0xffffffffu, sum, o);
    if (lane == 0) red1[wid] = sum;
    __syncthreads();
    float total;
    {
        // redundant per-warp reduce of the 8 partials (no extra barrier)
        float t = (lane < NWARPS) ? red1[lane] : 0.0f;
        #pragma unroll
        for (int o = 4; o > 0; o >>= 1) t += __shfl_down_sync(0xffffffffu, t, o);
        total = __shfl_sync(0xffffffffu, t, 0);
    }
    const float mean = total * (1.0f / (float)M);

    // ---- Pass 2 (registers only): s = sum exp(-k2), num = sum exp(-k2)*k2 ----
    float s = 0.0f, num = 0.0f;
    #pragma unroll
    for (int k = 0; k < VECS; k++) {
        float d0 = v[k].x - mean, d1 = v[k].y - mean,
              d2 = v[k].z - mean, d3 = v[k].w - mean;
        float a = d0 * d0, b = d1 * d1, c = d2 * d2, e4 = d3 * d3;
        float e0 = __expf(-a), e1 = __expf(-b), e2 = __expf(-c), e3 = __expf(-e4);
        s += ((e0 + e1) + (e2 + e3));
        num = fmaf(e0, a, num); num = fmaf(e1, b, num);
        num = fmaf(e2, c, num); num = fmaf(e3, e4, num);
    }

    // ---- Reduction 2: joint (s, num) ----
    #pragma unroll
    for (int o = 16; o > 0; o >>= 1) {
        s   += __shfl_down_sync(0xffffffffu, s, o);
        num += __shfl_down_sync(0xffffffffu, num, o);
    }
    if (lane == 0) red2[wid] = make_float2(s, num);
    __syncthreads();
    if (wid == 0 && lane < NWARPS) {
        float2 t = red2[lane];
        #pragma unroll
        for (int o = 4; o > 0; o >>= 1) {
            t.x += __shfl_down_sync(0xffffffffu, t.x, o);
            t.y += __shfl_down_sync(0xffffffffu, t.y, o);
        }
        if (lane == 0) out[blockIdx.x] = t.y / t.x;
    }
}

extern "C" void kernel_launch(void* const* d_in, const int* in_sizes, int n_in,
                              void* d_out, int out_size) {
    // d_in[0] = cdr3_features  [4, 2048, 1] (mathematically irrelevant; unused)
    // d_in[1] = all_atom_features [4, 8192, 1]
    const float4* atom4 = (const float4*)d_in[1];
    float* out = (float*)d_out;
    const int B = in_sizes[1] / M;   // 4
    invariant_cross_attention_kernel<<<B, NTHREADS>>>(atom4, out);
}